// round 5
// baseline (speedup 1.0000x reference)
#include <cuda_runtime.h>
#include <cuda_bf16.h>

#define B_  2
#define L_  24
#define C_  16
#define H_  64
#define W_  64
#define HW_ 4096
#define KCH 6

// Cumulative flow scratch: [B][L][HW] float2 (x,y interleaved per pixel).
__device__ float2 g_cum[(size_t)B_ * L_ * HW_];

// (t, k0) chunk table: for each t, chunks of <=KCH k-values. 60 entries.
__constant__ short2 g_chunks[60] = {
    {0,0},{1,0},{2,0},{3,0},{4,0},{5,0},
    {6,0},{6,6},{7,0},{7,6},{8,0},{8,6},{9,0},{9,6},{10,0},{10,6},{11,0},{11,6},
    {12,0},{12,6},{12,12},{13,0},{13,6},{13,12},{14,0},{14,6},{14,12},
    {15,0},{15,6},{15,12},{16,0},{16,6},{16,12},{17,0},{17,6},{17,12},
    {18,0},{18,6},{18,12},{18,18},{19,0},{19,6},{19,12},{19,18},
    {20,0},{20,6},{20,12},{20,18},{21,0},{21,6},{21,12},{21,18},
    {22,0},{22,6},{22,12},{22,18},{23,0},{23,6},{23,12},{23,18}
};

// cum[b,k,pix] = sum_{j<=k} flows[b,j,:,pix].  Thread per (b,pix), serial in k.
__global__ __launch_bounds__(256) void cum_kernel(
    const float* __restrict__ flows)    // [B, L, 2, H, W]
{
    const int pix = blockIdx.x * blockDim.x + threadIdx.x;   // 0..4095
    const int b   = blockIdx.y;
    const float* fp = flows + (size_t)b * L_ * 2 * HW_ + pix;
    float2* cp = g_cum + (size_t)b * L_ * HW_ + pix;

    float sx = 0.f, sy = 0.f;
#pragma unroll
    for (int k = 0; k < L_; ++k) {
        sx += fp[(size_t)k * 2 * HW_];
        sy += fp[(size_t)k * 2 * HW_ + HW_];
        cp[(size_t)k * HW_] = make_float2(sx, sy);
    }
}

// One bilinear-tap accumulation step for 8 channels.
__device__ __forceinline__ void gsp_step(
    int k, int w, int h, float2 cumt, const float2* __restrict__ cumb,
    const float* __restrict__ imgb, float acc[8])
{
    const float2 ckf = cumb[(size_t)k * HW_];
    float relx = cumt.x - ckf.x;   // exactly 0 when k==t
    float rely = cumt.y - ckf.y;

    // align_corners=False: base grid == pixel centers
    float ix = (float)w + 32.f * relx;
    ix -= 64.f * floorf((ix + 0.5f) * 0.015625f);   // wrap x into [-0.5, 63.5)
    float iy = (float)h + 32.f * rely;

    float x0f = floorf(ix), y0f = floorf(iy);
    int   x0  = (int)x0f,   y0  = (int)y0f;
    float wx1 = ix - x0f,   wy1 = iy - y0f;
    float wx0 = 1.f - wx1,  wy0 = 1.f - wy1;

    // x0 in [-1, 63] by construction; x1 = x0+1 in [0, 64]
    bool vx0 = (x0 >= 0);
    bool vx1 = (x0 < W_ - 1);
    bool vy0 = (y0 >= 0) && (y0 <= H_ - 1);
    bool vy1 = (y0 >= -1) && (y0 < H_ - 1);

    float w00 = wx0 * wy0 * (float)(vx0 && vy0);
    float w01 = wx1 * wy0 * (float)(vx1 && vy0);
    float w10 = wx0 * wy1 * (float)(vx0 && vy1);
    float w11 = wx1 * wy1 * (float)(vx1 && vy1);

    int cx0 = max(x0, 0),              cx1 = min(x0 + 1, W_ - 1);
    int cy0 = min(max(y0, 0), H_ - 1), cy1 = min(max(y0 + 1, 0), H_ - 1);

    const int o00 = cy0 * W_ + cx0, o01 = cy0 * W_ + cx1;
    const int o10 = cy1 * W_ + cx0, o11 = cy1 * W_ + cx1;

    const float* ib = imgb + (size_t)k * C_ * HW_;
#pragma unroll
    for (int c = 0; c < 8; ++c) {
        const float* p = ib + (size_t)c * HW_;
        acc[c] += w00 * p[o00] + w01 * p[o01] + w10 * p[o10] + w11 * p[o11];
    }
}

// out[b,t,c,h,w] += sum_{k in chunk} bilinear_sample(images[b,k,c],
//     pixel_center(h,w) + 32*(cum[t]-cum[k])),
// x wrapped into [-0.5, 63.5), zeros padding at borders.
// Block = (pixtile, chunk, b*2+half); every block does <= KCH k-iterations.
// Full chunks take a compile-time unrolled path (front-batched tap loads);
// t < KCH outputs have exactly one writer block -> plain stores, no atomics.
__global__ __launch_bounds__(256) void gsp_kernel(
    const float* __restrict__ images,   // [B, L, C, H, W]
    float* __restrict__ out)            // [B, L, C, H, W]
{
    const int b    = blockIdx.z >> 1;
    const int half = blockIdx.z & 1;          // channel half: 0 -> c0..7, 1 -> c8..15
    const short2 ck_ = g_chunks[blockIdx.y];
    const int t    = ck_.x;
    const int k0   = ck_.y;
    const int kend = min(k0 + KCH, t + 1);
    const int pix  = blockIdx.x * blockDim.x + threadIdx.x;   // 0..4095
    const int h    = pix >> 6;
    const int w    = pix & 63;

    float acc[8];
#pragma unroll
    for (int c = 0; c < 8; ++c) acc[c] = 0.f;

    const float2* cumb = g_cum + (size_t)b * L_ * HW_ + pix;
    const float2 cumt = cumb[(size_t)t * HW_];
    const float* imgb = images + ((size_t)b * L_) * C_ * HW_ + (size_t)half * 8 * HW_;

    if (kend - k0 == KCH) {
#pragma unroll
        for (int j = 0; j < KCH; ++j)
            gsp_step(k0 + j, w, h, cumt, cumb, imgb, acc);
    } else {
#pragma unroll 3
        for (int k = k0; k < kend; ++k)
            gsp_step(k, w, h, cumt, cumb, imgb, acc);
    }

    float* op = out + (((size_t)b * L_ + t) * C_ + half * 8) * HW_ + pix;
    if (t < KCH) {   // single writer: plain stores
#pragma unroll
        for (int c = 0; c < 8; ++c) op[(size_t)c * HW_] = acc[c];
    } else {
#pragma unroll
        for (int c = 0; c < 8; ++c) atomicAdd(op + (size_t)c * HW_, acc[c]);
    }
}

extern "C" void kernel_launch(void* const* d_in, const int* in_sizes, int n_in,
                              void* d_out, int out_size)
{
    const float* flows  = (const float*)d_in[0];   // [2,24,2,64,64]
    const float* images = (const float*)d_in[1];   // [2,24,16,64,64]
    float*       out    = (float*)d_out;           // [2,24,16,64,64]

    // Zero only the atomically-accumulated region (t >= KCH); t < KCH is
    // written with plain stores. Memset node is far cheaper than a kernel.
    size_t skip = (size_t)KCH * C_ * HW_;          // per-batch prefix done by stores
    for (int b = 0; b < B_; ++b) {
        float* p = out + (size_t)b * L_ * C_ * HW_;
        cudaMemsetAsync(p + skip, 0, ((size_t)L_ * C_ * HW_ - skip) * sizeof(float), 0);
    }

    dim3 cgrid(HW_ / 256, B_);                     // (16, 2)
    cum_kernel<<<cgrid, 256>>>(flows);

    dim3 grid(HW_ / 256, 60, B_ * 2);              // (16, 60, 4)
    gsp_kernel<<<grid, 256>>>(images, out);
}

// round 6
// speedup vs baseline: 1.0367x; 1.0367x over previous
#include <cuda_runtime.h>
#include <cuda_bf16.h>

#define B_  2
#define L_  24
#define C_  16
#define H_  64
#define W_  64
#define HW_ 4096
#define KCH 6

// Channel-grouped scratch: [B*L][4 groups][HW] float4 (4 channels per element).
__device__ float4 g_imgT[(size_t)B_ * L_ * 4 * HW_];
// Cumulative flow scratch: [B][L][HW] float2 (x,y per pixel).
__device__ float2 g_cum[(size_t)B_ * L_ * HW_];

// (t, k0) chunk table: for each t, chunks of <=KCH k-values. 60 entries.
__constant__ short2 g_chunks[60] = {
    {0,0},{1,0},{2,0},{3,0},{4,0},{5,0},
    {6,0},{6,6},{7,0},{7,6},{8,0},{8,6},{9,0},{9,6},{10,0},{10,6},{11,0},{11,6},
    {12,0},{12,6},{12,12},{13,0},{13,6},{13,12},{14,0},{14,6},{14,12},
    {15,0},{15,6},{15,12},{16,0},{16,6},{16,12},{17,0},{17,6},{17,12},
    {18,0},{18,6},{18,12},{18,18},{19,0},{19,6},{19,12},{19,18},
    {20,0},{20,6},{20,12},{20,18},{21,0},{21,6},{21,12},{21,18},
    {22,0},{22,6},{22,12},{22,18},{23,0},{23,6},{23,12},{23,18}
};

// NCHW -> channel-group-of-4 transpose. Thread per (pix, bl, group):
// 4 coalesced LDG.32 + 1 STG.128.
__global__ __launch_bounds__(256) void transpose_kernel(
    const float* __restrict__ images)
{
    const int pix = blockIdx.x * blockDim.x + threadIdx.x;   // 0..4095
    const int bl  = blockIdx.y;                              // 0..47
    const int grp = blockIdx.z;                              // 0..3
    const float* src = images + ((size_t)bl * C_ + grp * 4) * HW_ + pix;
    g_imgT[((size_t)bl * 4 + grp) * HW_ + pix] =
        make_float4(src[0], src[HW_], src[2 * HW_], src[3 * HW_]);
}

// cum[b,k,pix] = sum_{j<=k} flows[b,j,:,pix].
__global__ __launch_bounds__(256) void cum_kernel(
    const float* __restrict__ flows)    // [B, L, 2, H, W]
{
    const int pix = blockIdx.x * blockDim.x + threadIdx.x;
    const int b   = blockIdx.y;
    const float* fp = flows + (size_t)b * L_ * 2 * HW_ + pix;
    float2* cp = g_cum + (size_t)b * L_ * HW_ + pix;

    float sx = 0.f, sy = 0.f;
#pragma unroll
    for (int k = 0; k < L_; ++k) {
        sx += fp[(size_t)k * 2 * HW_];
        sy += fp[(size_t)k * 2 * HW_ + HW_];
        cp[(size_t)k * HW_] = make_float2(sx, sy);
    }
}

__device__ __forceinline__ void fma4(float4& a, float s, float4 v) {
    a.x += s * v.x; a.y += s * v.y; a.z += s * v.z; a.w += s * v.w;
}

// One bilinear-tap step for 8 channels (2 float4 groups).
__device__ __forceinline__ void gsp_step(
    int k, int w, int h, float2 cumt, const float2* __restrict__ cumb,
    const float4* __restrict__ g0base, float4& acc0, float4& acc1)
{
    const float2 ckf = cumb[(size_t)k * HW_];
    float relx = cumt.x - ckf.x;   // exactly 0 when k==t
    float rely = cumt.y - ckf.y;

    // align_corners=False: base grid == pixel centers
    float ix = (float)w + 32.f * relx;
    ix -= 64.f * floorf((ix + 0.5f) * 0.015625f);   // wrap x into [-0.5, 63.5)
    float iy = (float)h + 32.f * rely;

    float x0f = floorf(ix), y0f = floorf(iy);
    int   x0  = (int)x0f,   y0  = (int)y0f;
    float wx1 = ix - x0f,   wy1 = iy - y0f;
    float wx0 = 1.f - wx1,  wy0 = 1.f - wy1;

    // x0 in [-1, 63] by construction; x1 = x0+1 in [0, 64]
    bool vx0 = (x0 >= 0);
    bool vx1 = (x0 < W_ - 1);
    bool vy0 = (y0 >= 0) && (y0 <= H_ - 1);
    bool vy1 = (y0 >= -1) && (y0 < H_ - 1);

    float w00 = wx0 * wy0 * (float)(vx0 && vy0);
    float w01 = wx1 * wy0 * (float)(vx1 && vy0);
    float w10 = wx0 * wy1 * (float)(vx0 && vy1);
    float w11 = wx1 * wy1 * (float)(vx1 && vy1);

    int cx0 = max(x0, 0),              cx1 = min(x0 + 1, W_ - 1);
    int cy0 = min(max(y0, 0), H_ - 1), cy1 = min(max(y0 + 1, 0), H_ - 1);

    const int o00 = cy0 * W_ + cx0, o01 = cy0 * W_ + cx1;
    const int o10 = cy1 * W_ + cx0, o11 = cy1 * W_ + cx1;

    const float4* g0 = g0base + (size_t)k * 4 * HW_;   // group A plane for frame k
    const float4* g1 = g0 + HW_;                       // group B plane

    fma4(acc0, w00, g0[o00]); fma4(acc0, w01, g0[o01]);
    fma4(acc0, w10, g0[o10]); fma4(acc0, w11, g0[o11]);
    fma4(acc1, w00, g1[o00]); fma4(acc1, w01, g1[o01]);
    fma4(acc1, w10, g1[o10]); fma4(acc1, w11, g1[o11]);
}

// out[b,t,c,h,w] += sum_{k in chunk} bilinear taps (8 channels per thread).
// Block = (pixtile, chunk, b*2+half); <= KCH k-iterations per block.
__global__ __launch_bounds__(256) void gsp_kernel(
    float* __restrict__ out)            // [B, L, C, H, W]
{
    const int b    = blockIdx.z >> 1;
    const int half = blockIdx.z & 1;          // 0 -> groups 0,1 (c0..7); 1 -> groups 2,3
    const short2 ck_ = g_chunks[blockIdx.y];
    const int t    = ck_.x;
    const int k0   = ck_.y;
    const int kend = min(k0 + KCH, t + 1);
    const int pix  = blockIdx.x * blockDim.x + threadIdx.x;
    const int h    = pix >> 6;
    const int w    = pix & 63;

    float4 acc0 = make_float4(0.f, 0.f, 0.f, 0.f);
    float4 acc1 = make_float4(0.f, 0.f, 0.f, 0.f);

    const float2* cumb = g_cum + (size_t)b * L_ * HW_ + pix;
    const float2 cumt = cumb[(size_t)t * HW_];
    // plane base for (b, frame 0, group half*2)
    const float4* g0base = g_imgT + ((size_t)b * L_ * 4 + half * 2) * HW_;

    if (kend - k0 == KCH) {
#pragma unroll
        for (int j = 0; j < KCH; ++j)
            gsp_step(k0 + j, w, h, cumt, cumb, g0base, acc0, acc1);
    } else {
#pragma unroll 3
        for (int k = k0; k < kend; ++k)
            gsp_step(k, w, h, cumt, cumb, g0base, acc0, acc1);
    }

    float* op = out + (((size_t)b * L_ + t) * C_ + half * 8) * HW_ + pix;
    float a[8] = {acc0.x, acc0.y, acc0.z, acc0.w, acc1.x, acc1.y, acc1.z, acc1.w};
    if (t < KCH) {   // single writer: plain stores
#pragma unroll
        for (int c = 0; c < 8; ++c) op[(size_t)c * HW_] = a[c];
    } else {
#pragma unroll
        for (int c = 0; c < 8; ++c) atomicAdd(op + (size_t)c * HW_, a[c]);
    }
}

extern "C" void kernel_launch(void* const* d_in, const int* in_sizes, int n_in,
                              void* d_out, int out_size)
{
    const float* flows  = (const float*)d_in[0];   // [2,24,2,64,64]
    const float* images = (const float*)d_in[1];   // [2,24,16,64,64]
    float*       out    = (float*)d_out;           // [2,24,16,64,64]

    // Zero only the atomically-accumulated region (t >= KCH).
    size_t skip = (size_t)KCH * C_ * HW_;
    for (int b = 0; b < B_; ++b) {
        float* p = out + (size_t)b * L_ * C_ * HW_;
        cudaMemsetAsync(p + skip, 0, ((size_t)L_ * C_ * HW_ - skip) * sizeof(float), 0);
    }

    dim3 tgrid(HW_ / 256, B_ * L_, 4);             // (16, 48, 4)
    transpose_kernel<<<tgrid, 256>>>(images);

    dim3 cgrid(HW_ / 256, B_);                     // (16, 2)
    cum_kernel<<<cgrid, 256>>>(flows);

    dim3 grid(HW_ / 256, 60, B_ * 2);              // (16, 60, 4)
    gsp_kernel<<<grid, 256>>>(out);
}